// round 17
// baseline (speedup 1.0000x reference)
#include <cuda_runtime.h>
#include <cuda_fp16.h>
#include <math.h>
#include <stdint.h>

#define BB 4
#define SS 4096
#define DIN 1024
#define DOUT 64
#define NROWS (BB*SS)          // 16384

#define NQT (SS/128)           // 32 query tiles of 128 rows per batch
#define CHUNK 512              // keys per split-KV chunk
#define MAXCH 8
#define NPART (BB*NQT*MAXCH)   // 1024

#define KST 72                 // tile row stride (f16 elems)
#define PLANE_ELEMS (64*KST)   // 4608 per plane
#define TILE2_BYTES (2*PLANE_ELEMS*2)   // 18432 B per tile (K + Vt)

// Scratch (no allocation allowed in kernel_launch)
__device__ float g_q[NROWS*DOUT];
__device__ float g_pacc[(size_t)NPART*128*DOUT];
__device__ float g_pl[NPART*128];
// Pre-split weights (fp16): [mat][n][k], k-contiguous
__device__ __half g_wt[3*64*1024];
// Pre-converted KV tiles (fp16): [global_row/64][plane][4608]
//   plane 0 = K [key][d], 1 = Vt [d][key]   (written by qkv epilogue)
__device__ __half g_tiles[(size_t)BB*64*2*PLANE_ELEMS];

// ---------------------------------------------------------------------------
// fp16 helpers: cvtf2 packs first arg into LOW 16 bits (even element)
// ---------------------------------------------------------------------------
__device__ __forceinline__ uint32_t cvtf2(float lo, float hi) {
    uint32_t r;
    asm("cvt.rn.f16x2.f32 %0, %1, %2;" : "=r"(r) : "f"(hi), "f"(lo));
    return r;
}

__device__ __forceinline__ uint32_t smem_u32(const void* p) {
    uint32_t a;
    asm("{ .reg .u64 t; cvta.to.shared.u64 t, %1; cvt.u32.u64 %0, t; }"
        : "=r"(a) : "l"(p));
    return a;
}

// mma.sync m16n8k16 row.col f16 -> f32 (frag layout validated r5-16)
__device__ __forceinline__ void mma_f16(float* d, uint32_t a0, uint32_t a1,
                                        uint32_t a2, uint32_t a3,
                                        uint32_t b0, uint32_t b1) {
    asm("mma.sync.aligned.m16n8k16.row.col.f32.f16.f16.f32 "
        "{%0,%1,%2,%3}, {%4,%5,%6,%7}, {%8,%9}, {%0,%1,%2,%3};"
        : "+f"(d[0]), "+f"(d[1]), "+f"(d[2]), "+f"(d[3])
        : "r"(a0), "r"(a1), "r"(a2), "r"(a3), "r"(b0), "r"(b1));
}

// ldmatrix m8n8.x4 (validated r9-r16)
__device__ __forceinline__ void ldm_x4(uint32_t& r0, uint32_t& r1,
                                       uint32_t& r2, uint32_t& r3, uint32_t addr) {
    asm volatile("ldmatrix.sync.aligned.m8n8.x4.shared.b16 {%0,%1,%2,%3}, [%4];"
                 : "=r"(r0), "=r"(r1), "=r"(r2), "=r"(r3) : "r"(addr));
}

// ---------------------------------------------------------------------------
// Kernel 0: convert W to fp16, transposed to [mat][n][k] (k-contiguous)
// ---------------------------------------------------------------------------
__global__ __launch_bounds__(256) void prep_w_kernel(
    const float* __restrict__ Wq, const float* __restrict__ Wk,
    const float* __restrict__ Wv)
{
    int idx = blockIdx.x * 256 + threadIdx.x;     // 0 .. 196607
    int mat = idx >> 16;
    int r   = idx & 65535;
    const float* W = (mat == 0) ? Wq : (mat == 1) ? Wk : Wv;
    float w = W[r];                                // coalesced read: r = k*64+n
    int k = r >> 6;
    int n = r & 63;
    g_wt[(mat << 16) + n * 1024 + k] = __float2half(w);
}

// ---------------------------------------------------------------------------
// Kernel 1: QKV — 128 rows/block, 256 threads (8 warps), grid (3, 128).
// Halves W staging traffic and per-row barrier count vs the 64-row version.
// Mainloop math identical to r14/r16. Fused tile epilogue (2 tiles/block):
//   mat 0 -> g_q fp32; mat 1 -> K planes; mat 2 -> Vt planes via smem transpose
// ---------------------------------------------------------------------------
#define QWTS 40   // f16 elements per smem B row (80B stride)
#define QBUF (64*QWTS)   // 2560 halves = 5120 B per buffer

__global__ __launch_bounds__(256) void qkv_mma_kernel(
    const float* __restrict__ x,
    const float* __restrict__ bq, const float* __restrict__ bk,
    const float* __restrict__ bv)
{
    __shared__ __align__(16) __half bs[2 * QBUF];    // 10240 B
    __shared__ __align__(16) __half vsm[128 * KST];  // 18432 B (V transpose stage)

    int tid  = threadIdx.x;
    int wid  = tid >> 5;      // 0..7
    int lane = tid & 31;
    int g    = lane >> 2;     // 0..7
    int t    = lane & 3;      // 0..3
    int mat  = blockIdx.x;
    int bt2  = blockIdx.y * 2;             // first of two attention tiles
    int r0   = blockIdx.y * 128;
    int lrow = wid * 16 + g;               // local rows lrow and lrow+8 (0..127)
    int rA   = r0 + lrow;

    const __half* wsrc = &g_wt[mat << 16];
    const float* bias = (mat == 0) ? bq : (mat == 1) ? bk : bv;

    uint32_t bbase = smem_u32(bs);
    uint32_t laneoff = (((lane >> 4) * 8 + (lane & 7)) * QWTS) * 2
                       + (((lane >> 3) & 1) * 8) * 2;

    float acc[8][4];
#pragma unroll
    for (int nt = 0; nt < 8; nt++)
#pragma unroll
        for (int i = 0; i < 4; i++) acc[nt][i] = 0.f;

    const float* xlo = &x[(size_t)rA * DIN];
    const float* xhi = &x[(size_t)(rA + 8) * DIN];

    // prologue: stage chunk 0 into buffer 0 (256 uint4 = 4096B of W data)
    {
        int i = tid;               // one uint4 per thread
        int row = i >> 2;
        int cc  = i & 3;
        asm volatile("cp.async.cg.shared.global [%0], [%1], 16;"
                     :: "r"(bbase + (row * QWTS + cc * 8) * 2),
                        "l"((const char*)&wsrc[row * 1024 + cc * 8])
                     : "memory");
    }
    asm volatile("cp.async.commit_group;" ::: "memory");

    int ib = 0;
    for (int c = 0; c < 32; c++, ib ^= 1) {
        if (c + 1 < 32) {
            int c0n = (c + 1) * 32;
            uint32_t nb = bbase + (ib ^ 1) * QBUF * 2;
            int i = tid;
            int row = i >> 2;
            int cc  = i & 3;
            asm volatile("cp.async.cg.shared.global [%0], [%1], 16;"
                         :: "r"(nb + (row * QWTS + cc * 8) * 2),
                            "l"((const char*)&wsrc[row * 1024 + c0n + cc * 8])
                         : "memory");
            asm volatile("cp.async.commit_group;" ::: "memory");
            asm volatile("cp.async.wait_group 1;" ::: "memory");
        } else {
            asm volatile("cp.async.wait_group 0;" ::: "memory");
        }
        __syncthreads();

        uint32_t bufb = bbase + ib * QBUF * 2;
        int c0 = c * 32;
#pragma unroll
        for (int ks = 0; ks < 2; ks++) {
            int kk = c0 + ks * 16;
            float2 xa = *(const float2*)&xlo[kk + 2 * t];
            float2 xb = *(const float2*)&xlo[kk + 2 * t + 8];
            float2 xc = *(const float2*)&xhi[kk + 2 * t];
            float2 xd = *(const float2*)&xhi[kk + 2 * t + 8];
            uint32_t a0 = cvtf2(xa.x, xa.y);
            uint32_t a1 = cvtf2(xc.x, xc.y);
            uint32_t a2 = cvtf2(xb.x, xb.y);
            uint32_t a3 = cvtf2(xd.x, xd.y);

#pragma unroll
            for (int np = 0; np < 4; np++) {     // nt pair 2np, 2np+1
                uint32_t off = (np * 16 * QWTS + ks * 16) * 2;
                uint32_t b0a, b1a, b0b, b1b;
                ldm_x4(b0a, b1a, b0b, b1b, bufb + off + laneoff);
                mma_f16(acc[2*np],   a0, a1, a2, a3, b0a, b1a);
                mma_f16(acc[2*np+1], a0, a1, a2, a3, b0b, b1b);
            }
        }
        __syncthreads();
    }

    // ---- epilogue ----
    if (mat == 0) {
#pragma unroll
        for (int nt = 0; nt < 8; nt++) {
            int col = nt * 8 + 2 * t;
            float b0 = bias[col], b1 = bias[col + 1];
            float2 o0 = make_float2(acc[nt][0] + b0, acc[nt][1] + b1);
            float2 o1 = make_float2(acc[nt][2] + b0, acc[nt][3] + b1);
            *(float2*)&g_q[(size_t)rA * DOUT + col] = o0;
            *(float2*)&g_q[(size_t)(rA + 8) * DOUT + col] = o1;
        }
    } else if (mat == 1) {
        // K: fp16 + bias directly into K planes ([key][d]); rows may span tiles
        int r1 = lrow, r2 = lrow + 8;
        __half* tkA = &g_tiles[(size_t)(bt2 + (r1 >> 6)) * 2 * PLANE_ELEMS];
        __half* tkB = &g_tiles[(size_t)(bt2 + (r2 >> 6)) * 2 * PLANE_ELEMS];
        int lr1 = (r1 & 63) * KST, lr2 = (r2 & 63) * KST;
#pragma unroll
        for (int nt = 0; nt < 8; nt++) {
            int col = nt * 8 + 2 * t;
            float b0 = bias[col], b1 = bias[col + 1];
            uint32_t h0 = cvtf2(acc[nt][0] + b0, acc[nt][1] + b1);
            uint32_t h1 = cvtf2(acc[nt][2] + b0, acc[nt][3] + b1);
            *(uint32_t*)&tkA[lr1 + col] = h0;
            *(uint32_t*)&tkB[lr2 + col] = h1;
        }
    } else {
        // V: fp16 + bias into smem [key][d], then transposed write to Vt planes
#pragma unroll
        for (int nt = 0; nt < 8; nt++) {
            int col = nt * 8 + 2 * t;
            float b0 = bias[col], b1 = bias[col + 1];
            uint32_t h0 = cvtf2(acc[nt][0] + b0, acc[nt][1] + b1);
            uint32_t h1 = cvtf2(acc[nt][2] + b0, acc[nt][3] + b1);
            *(uint32_t*)&vsm[lrow * KST + col]       = h0;
            *(uint32_t*)&vsm[(lrow + 8) * KST + col] = h1;
        }
        __syncthreads();
        // transposed write: thread -> d = tid>>2, keys kq..kq+31 (kq = (tid&3)*32)
        int d  = tid >> 2;
        int kq = (tid & 3) * 32;
        __half* tv = &g_tiles[(size_t)(bt2 + (kq >> 6)) * 2 * PLANE_ELEMS
                              + PLANE_ELEMS];
        int lkq = kq & 63;
        uint32_t hp[16];
#pragma unroll
        for (int i = 0; i < 16; i++) {
            int key = kq + 2 * i;
            uint32_t u0 = (uint32_t)__half_as_ushort(vsm[key * KST + d]);
            uint32_t u1 = (uint32_t)__half_as_ushort(vsm[(key + 1) * KST + d]);
            hp[i] = u0 | (u1 << 16);
        }
        uint4* dst = (uint4*)&tv[d * KST + lkq];
#pragma unroll
        for (int i = 0; i < 4; i++)
            dst[i] = make_uint4(hp[4*i], hp[4*i+1], hp[4*i+2], hp[4*i+3]);
    }
}

// ---------------------------------------------------------------------------
// Kernel 2: flash-attention partial, fp16 single-pass (UNCHANGED; 38.3us)
// ---------------------------------------------------------------------------
__global__ __launch_bounds__(256, 2) void attn_mma_kernel()
{
    extern __shared__ __align__(16) char smdyn[];

    int blk = blockIdx.x;
    int b   = blk / (NQT * MAXCH);
    int rem = blk % (NQT * MAXCH);
    int qt  = rem / MAXCH;
    int ch  = rem % MAXCH;
    int nch = (qt >> 2) + 1;   // ceil((qt+1)*128 / 512)
    if (ch >= nch) return;

    int tid  = threadIdx.x;
    int w    = tid >> 5;
    int lane = tid & 31;
    int g    = lane >> 2;
    int t    = lane & 3;

    int rg  = qt * 128 + w * 16 + g;   // query rows rg and rg+8
    int rg8 = rg + 8;
    int rwmin = qt * 128 + w * 16;     // min row in this warp's tile

    uint32_t smT_base = smem_u32(smdyn);
    uint32_t laneoff = ((((lane >> 4) * 8 + (lane & 7)) * KST
                         + ((lane >> 3) & 1) * 8) * 2);

    const float SCALE = 0.015625f;   // 1/sqrt(4096)
    uint32_t qh[4][4];
    {
        const float* q0 = &g_q[((size_t)b * SS + rg) * DOUT];
        const float* q8 = &g_q[((size_t)b * SS + rg8) * DOUT];
#pragma unroll
        for (int ks = 0; ks < 4; ks++) {
            float2 xa = *(const float2*)&q0[ks * 16 + 2 * t];
            float2 xc = *(const float2*)&q8[ks * 16 + 2 * t];
            float2 xb = *(const float2*)&q0[ks * 16 + 2 * t + 8];
            float2 xd = *(const float2*)&q8[ks * 16 + 2 * t + 8];
            qh[ks][0] = cvtf2(xa.x * SCALE, xa.y * SCALE);
            qh[ks][1] = cvtf2(xc.x * SCALE, xc.y * SCALE);
            qh[ks][2] = cvtf2(xb.x * SCALE, xb.y * SCALE);
            qh[ks][3] = cvtf2(xd.x * SCALE, xd.y * SCALE);
        }
    }

    float o[8][4];
#pragma unroll
    for (int nd = 0; nd < 8; nd++)
#pragma unroll
        for (int i = 0; i < 4; i++) o[nd][i] = 0.f;
    float lg = 0.f, lg8 = 0.f;

    int k0 = ch * CHUNK;
    int k1 = min(k0 + CHUNK, (qt + 1) * 128);

    {
        const char* src =
            (const char*)&g_tiles[(size_t)(b * 64 + (k0 >> 6)) * 2 * PLANE_ELEMS];
        for (int i = tid; i < 1152; i += 256) {
            asm volatile("cp.async.cg.shared.global [%0], [%1], 16;"
                         :: "r"(smT_base + i * 16), "l"(src + (size_t)i * 16)
                         : "memory");
        }
        asm volatile("cp.async.commit_group;" ::: "memory");
    }

    int ib = 0;
    for (int kt = k0; kt < k1; kt += 64, ib ^= 1) {
        int ktn = kt + 64;
        if (ktn < k1) {
            uint32_t nb = smT_base + (ib ^ 1) * TILE2_BYTES;
            const char* src =
                (const char*)&g_tiles[(size_t)(b * 64 + (ktn >> 6)) * 2 * PLANE_ELEMS];
            for (int i = tid; i < 1152; i += 256) {
                asm volatile("cp.async.cg.shared.global [%0], [%1], 16;"
                             :: "r"(nb + i * 16), "l"(src + (size_t)i * 16)
                             : "memory");
            }
            asm volatile("cp.async.commit_group;" ::: "memory");
            asm volatile("cp.async.wait_group 1;" ::: "memory");
        } else {
            asm volatile("cp.async.wait_group 0;" ::: "memory");
        }
        __syncthreads();

        uint32_t bufb = smT_base + ib * TILE2_BYTES;
        uint32_t aK = bufb + laneoff;
        uint32_t aV = bufb + PLANE_ELEMS * 2 + laneoff;

        float c[8][4];
#pragma unroll
        for (int nc = 0; nc < 8; nc++)
#pragma unroll
            for (int i = 0; i < 4; i++) c[nc][i] = 0.f;

#pragma unroll
        for (int ks = 0; ks < 4; ks++) {
#pragma unroll
            for (int np = 0; np < 4; np++) {
                uint32_t off = (np * 16 * KST + ks * 16) * 2;
                uint32_t b0a, b1a, b0b, b1b;
                ldm_x4(b0a, b1a, b0b, b1b, aK + off);
                mma_f16(c[2*np],   qh[ks][0], qh[ks][1], qh[ks][2], qh[ks][3], b0a, b1a);
                mma_f16(c[2*np+1], qh[ks][0], qh[ks][1], qh[ks][2], qh[ks][3], b0b, b1b);
            }
        }

        uint32_t pah[4][4];
        if (kt + 63 <= rwmin) {
#pragma unroll
            for (int nc = 0; nc < 8; nc++) {
                float e0 = __expf(c[nc][0]);
                float e1 = __expf(c[nc][1]);
                float e2 = __expf(c[nc][2]);
                float e3 = __expf(c[nc][3]);
                lg  += e0 + e1;
                lg8 += e2 + e3;
                uint32_t h01 = cvtf2(e0, e1), h23 = cvtf2(e2, e3);
                int j = nc >> 1;
                if ((nc & 1) == 0) { pah[j][0] = h01; pah[j][1] = h23; }
                else               { pah[j][2] = h01; pah[j][3] = h23; }
            }
        } else {
#pragma unroll
            for (int nc = 0; nc < 8; nc++) {
                int col0 = kt + nc * 8 + 2 * t;
                int col1 = col0 + 1;
                float e0 = (col0 <= rg)  ? __expf(c[nc][0]) : 0.f;
                float e1 = (col1 <= rg)  ? __expf(c[nc][1]) : 0.f;
                float e2 = (col0 <= rg8) ? __expf(c[nc][2]) : 0.f;
                float e3 = (col1 <= rg8) ? __expf(c[nc][3]) : 0.f;
                lg  += e0 + e1;
                lg8 += e2 + e3;
                uint32_t h01 = cvtf2(e0, e1), h23 = cvtf2(e2, e3);
                int j = nc >> 1;
                if ((nc & 1) == 0) { pah[j][0] = h01; pah[j][1] = h23; }
                else               { pah[j][2] = h01; pah[j][3] = h23; }
            }
        }

#pragma unroll
        for (int j = 0; j < 4; j++) {
#pragma unroll
            for (int np = 0; np < 4; np++) {
                uint32_t off = (np * 16 * KST + j * 16) * 2;
                uint32_t b0a, b1a, b0b, b1b;
                ldm_x4(b0a, b1a, b0b, b1b, aV + off);
                mma_f16(o[2*np],   pah[j][0], pah[j][1], pah[j][2], pah[j][3], b0a, b1a);
                mma_f16(o[2*np+1], pah[j][0], pah[j][1], pah[j][2], pah[j][3], b0b, b1b);
            }
        }
        __syncthreads();
    }

    lg  += __shfl_xor_sync(0xffffffffu, lg, 1);
    lg  += __shfl_xor_sync(0xffffffffu, lg, 2);
    lg8 += __shfl_xor_sync(0xffffffffu, lg8, 1);
    lg8 += __shfl_xor_sync(0xffffffffu, lg8, 2);

    int pidx = (b * NQT + qt) * MAXCH + ch;
    int rl = w * 16 + g;
    if (t == 0) {
        g_pl[pidx * 128 + rl]     = lg;
        g_pl[pidx * 128 + rl + 8] = lg8;
    }
    float* pa0 = &g_pacc[((size_t)pidx * 128 + rl) * DOUT];
    float* pa8 = &g_pacc[((size_t)pidx * 128 + rl + 8) * DOUT];
#pragma unroll
    for (int nd = 0; nd < 8; nd++) {
        *(float2*)&pa0[nd * 8 + 2 * t] = make_float2(o[nd][0], o[nd][1]);
        *(float2*)&pa8[nd * 8 + 2 * t] = make_float2(o[nd][2], o[nd][3]);
    }
}

// ---------------------------------------------------------------------------
// Kernel 3: combine split-KV partials — float4 loads, unrolled independent
// chunk reads for MLP. 256 threads = 16 rows x 16 float4-lanes.
// ---------------------------------------------------------------------------
__global__ __launch_bounds__(256) void combine_kernel(float* __restrict__ out)
{
    int tid  = threadIdx.x;
    int rowg = blockIdx.x * 16 + (tid >> 4);
    int b    = rowg / SS;
    int row  = rowg % SS;
    int qt   = row >> 7;
    int r    = row & 127;
    int nch  = (qt >> 2) + 1;
    int d4   = (tid & 15) * 4;
    int pbase = (b * NQT + qt) * MAXCH;

    float L = 0.f;
    float4 o = make_float4(0.f, 0.f, 0.f, 0.f);
#pragma unroll
    for (int c = 0; c < MAXCH; c++) {
        if (c < nch) {
            L += g_pl[(pbase + c) * 128 + r];
            float4 p = *(const float4*)
                &g_pacc[((size_t)(pbase + c) * 128 + r) * DOUT + d4];
            o.x += p.x; o.y += p.y; o.z += p.z; o.w += p.w;
        }
    }
    float inv = 1.f / L;
    float4 res = make_float4(o.x * inv, o.y * inv, o.z * inv, o.w * inv);
    *(float4*)&out[((size_t)b * SS + row) * DOUT + d4] = res;
}

// ---------------------------------------------------------------------------
extern "C" void kernel_launch(void* const* d_in, const int* in_sizes, int n_in,
                              void* d_out, int out_size)
{
    const float* x  = (const float*)d_in[0];
    const float* Wq = (const float*)d_in[1];
    const float* bq = (const float*)d_in[2];
    const float* Wk = (const float*)d_in[3];
    const float* bk = (const float*)d_in[4];
    const float* Wv = (const float*)d_in[5];
    const float* bv = (const float*)d_in[6];
    float* out = (float*)d_out;

    cudaFuncSetAttribute(attn_mma_kernel,
                         cudaFuncAttributeMaxDynamicSharedMemorySize,
                         2 * TILE2_BYTES);

    prep_w_kernel<<<768, 256>>>(Wq, Wk, Wv);
    dim3 gq(3, NROWS / 128);   // 128 rows/block, block covers two attn tiles
    qkv_mma_kernel<<<gq, 256>>>(x, bq, bk, bv);
    attn_mma_kernel<<<NPART, 256, 2 * TILE2_BYTES>>>();
    combine_kernel<<<NROWS / 16, 256>>>(out);
}